// round 5
// baseline (speedup 1.0000x reference)
#include <cuda_runtime.h>

#define NN 50000
#define DD 128
#define EE 800000

// Scratch (device globals — no allocation allowed)
__device__ __align__(256) float g_agg[NN * DD];
__device__ __align__(256) float g_h0[NN * DD];
__device__ __align__(256) float g_h1[NN * DD];
__device__ __align__(256) float g_inv[NN];
__device__ __align__(256) int   g_cnt[NN];
__device__ __align__(256) float g_wsum[DD * DD * 2 + DD * 64];  // folded Wr+Ws per layer
__device__ __align__(256) float g_bsum[DD + DD + 64];           // folded bl+bs per layer
__device__ int g_is32;   // 1 if edge_index is int32, 0 if int64

// ---------------------------------------------------------------------------
// Detect edge_index dtype: int32 data read as int64 produces huge values
// whenever the packed high word (the next index) is nonzero.
// ---------------------------------------------------------------------------
__global__ void detect_kernel(const long long* __restrict__ ei) {
    if (blockIdx.x == 0 && threadIdx.x == 0) {
        int is32 = 0;
        for (int i = 0; i < 64; ++i) {
            long long v = ei[i];
            if (v < 0 || v >= NN) { is32 = 1; break; }
        }
        g_is32 = is32;
    }
}

__device__ __forceinline__ void load_edge(const void* ei, int e, int& src, int& dst) {
    if (g_is32) {
        const int* p = (const int*)ei;
        src = p[e];
        dst = p[EE + e];
    } else {
        const long long* p = (const long long*)ei;
        src = (int)p[e];
        dst = (int)p[EE + e];
    }
}

// ---------------------------------------------------------------------------
// Prep: fold Wr+Ws and bl+bs for all 3 layers
// ---------------------------------------------------------------------------
__global__ void prep_kernel(const float* __restrict__ Wr0, const float* __restrict__ Ws0,
                            const float* __restrict__ Wr1, const float* __restrict__ Ws1,
                            const float* __restrict__ Wr2, const float* __restrict__ Ws2,
                            const float* __restrict__ bl0, const float* __restrict__ bs0,
                            const float* __restrict__ bl1, const float* __restrict__ bs1,
                            const float* __restrict__ bl2, const float* __restrict__ bs2) {
    int t = blockIdx.x * blockDim.x + threadIdx.x;
    const int n0 = DD * DD;              // 16384
    if (t < n0)                  g_wsum[t] = Wr0[t] + Ws0[t];
    else if (t < 2 * n0)         g_wsum[t] = Wr1[t - n0] + Ws1[t - n0];
    else if (t < 2 * n0 + DD*64) g_wsum[t] = Wr2[t - 2 * n0] + Ws2[t - 2 * n0];

    if (t < DD)                  g_bsum[t] = bl0[t] + bs0[t];
    else if (t < 2 * DD)         g_bsum[t] = bl1[t - DD] + bs1[t - DD];
    else if (t < 2 * DD + 64)    g_bsum[t] = bl2[t - 2 * DD] + bs2[t - 2 * DD];
}

// ---------------------------------------------------------------------------
// Degree counts (once per launch)
// ---------------------------------------------------------------------------
__global__ void zero_cnt_kernel() {
    int t = blockIdx.x * blockDim.x + threadIdx.x;
    if (t < NN) g_cnt[t] = 0;
}

__global__ void count_kernel(const void* __restrict__ ei) {
    int e = blockIdx.x * blockDim.x + threadIdx.x;
    if (e < EE) {
        int src, dst;
        load_edge(ei, e, src, dst);
        atomicAdd(&g_cnt[dst], 1);
    }
}

__global__ void inv_kernel() {
    int t = blockIdx.x * blockDim.x + threadIdx.x;
    if (t < NN) g_inv[t] = 1.0f / fmaxf((float)g_cnt[t], 1.0f);
}

// ---------------------------------------------------------------------------
// Zero the aggregation buffer
// ---------------------------------------------------------------------------
__global__ void zero_agg_kernel() {
    int t = blockIdx.x * blockDim.x + threadIdx.x;   // exactly NN*DD/4 threads
    ((float4*)g_agg)[t] = make_float4(0.f, 0.f, 0.f, 0.f);
}

// ---------------------------------------------------------------------------
// Scatter: 128 threads per edge (4 warps), one scalar atomicAdd per thread.
// Edge id is uniform within each warp -> index loads broadcast; each warp
// issues a fully coalesced 128B gather + 128B RED wavefront.
// SRC selector: 0 = external pointer (x), 1 = g_h0, 2 = g_h1
// ---------------------------------------------------------------------------
template<int SRC>
__global__ void scatter_kernel(const float* __restrict__ hx, const void* __restrict__ ei) {
    int gt = blockIdx.x * blockDim.x + threadIdx.x;
    int e = gt >> 7;          // edge id (uniform per 4 consecutive warps)
    int c = gt & 127;         // feature index
    const float* h = (SRC == 0) ? hx : (SRC == 1) ? g_h0 : g_h1;
    int src, dst;
    load_edge(ei, e, src, dst);
    float v = h[src * DD + c];
    atomicAdd(&g_agg[dst * DD + c], v);
}

// ---------------------------------------------------------------------------
// Fused GEMM: C = (g_agg * g_inv) @ Wl + A @ (Wr+Ws) + (bl+bs), optional relu
// BM=128, BN = DO (128 or 64), BK=16, 256 threads, 8xTN register tiles.
// SRC selector for A: 0 = external (x), 1 = g_h0, 2 = g_h1
// DST selector for C: 0 = external (out), 1 = g_h0, 2 = g_h1
// ---------------------------------------------------------------------------
template<int BN, int SRC, int DST, int RELU>
__global__ void gemm_kernel(const float* __restrict__ Ax_ext,
                            const float* __restrict__ B0,   // Wl (external)
                            int woff, int boff,
                            float* __restrict__ C_ext) {
    constexpr int TN = BN / 16;          // 8 for BN=128, 4 for BN=64
    __shared__ float As[16][132];        // [k][m], padded
    __shared__ float Bs[16][BN];         // [k][n]

    const float* Ax = (SRC == 0) ? Ax_ext : (SRC == 1) ? g_h0 : g_h1;
    float* C = (DST == 0) ? C_ext : (DST == 1) ? g_h0 : g_h1;
    const float* B1 = g_wsum + woff;
    const float* bias = g_bsum + boff;

    int t  = threadIdx.x;
    int tx = t & 15;
    int ty = t >> 4;
    int row0 = blockIdx.x * 128;

    float acc[8][TN];
    #pragma unroll
    for (int i = 0; i < 8; i++)
        #pragma unroll
        for (int j = 0; j < TN; j++) acc[i][j] = 0.f;

    #pragma unroll 1
    for (int phase = 0; phase < 2; ++phase) {
        const float* A = phase ? Ax : (const float*)g_agg;
        const float* B = phase ? B1 : B0;
        #pragma unroll 1
        for (int k0 = 0; k0 < 128; k0 += 16) {
            // --- load A tile (128 rows x 16 k), transposed into As[k][m]
            #pragma unroll
            for (int i = 0; i < 2; ++i) {
                int idx = t + i * 256;           // 0..511
                int r   = idx >> 2;              // 0..127
                int kq  = idx & 3;               // 0..3
                int grow = row0 + r;
                float4 v = make_float4(0.f, 0.f, 0.f, 0.f);
                if (grow < NN) {
                    v = *(const float4*)(A + (size_t)grow * DD + k0 + kq * 4);
                    if (phase == 0) {
                        float s = g_inv[grow];
                        v.x *= s; v.y *= s; v.z *= s; v.w *= s;
                    }
                }
                As[kq * 4 + 0][r] = v.x;
                As[kq * 4 + 1][r] = v.y;
                As[kq * 4 + 2][r] = v.z;
                As[kq * 4 + 3][r] = v.w;
            }
            // --- load B tile (16 k x BN cols)
            #pragma unroll
            for (int i = 0; i < (16 * BN) / (256 * 4); ++i) {
                int idx = t + i * 256;           // float4 index
                int r   = idx / (BN / 4);
                int jq  = idx % (BN / 4);
                float4 v = *(const float4*)(B + (k0 + r) * BN + jq * 4);
                *(float4*)&Bs[r][jq * 4] = v;
            }
            __syncthreads();
            // --- compute
            #pragma unroll
            for (int k = 0; k < 16; ++k) {
                float a[8], b[TN];
                *(float4*)&a[0] = *(float4*)&As[k][ty * 8];
                *(float4*)&a[4] = *(float4*)&As[k][ty * 8 + 4];
                *(float4*)&b[0] = *(float4*)&Bs[k][tx * TN];
                if (TN == 8) *(float4*)&b[4] = *(float4*)&Bs[k][tx * TN + 4];
                #pragma unroll
                for (int i = 0; i < 8; i++)
                    #pragma unroll
                    for (int j = 0; j < TN; j++)
                        acc[i][j] += a[i] * b[j];
            }
            __syncthreads();
        }
    }

    // --- epilogue: bias + relu + store
    float bv[TN];
    #pragma unroll
    for (int j = 0; j < TN; j++) bv[j] = bias[tx * TN + j];
    #pragma unroll
    for (int i = 0; i < 8; i++) {
        int grow = row0 + ty * 8 + i;
        if (grow < NN) {
            #pragma unroll
            for (int j = 0; j < TN; j += 4) {
                float4 v;
                v.x = acc[i][j + 0] + bv[j + 0];
                v.y = acc[i][j + 1] + bv[j + 1];
                v.z = acc[i][j + 2] + bv[j + 2];
                v.w = acc[i][j + 3] + bv[j + 3];
                if (RELU) {
                    v.x = fmaxf(v.x, 0.f); v.y = fmaxf(v.y, 0.f);
                    v.z = fmaxf(v.z, 0.f); v.w = fmaxf(v.w, 0.f);
                }
                *(float4*)(C + (size_t)grow * BN + tx * TN + j) = v;
            }
        }
    }
}

// ---------------------------------------------------------------------------
extern "C" void kernel_launch(void* const* d_in, const int* in_sizes, int n_in,
                              void* d_out, int out_size) {
    const float* x  = (const float*)d_in[0];
    const void*  ei = d_in[1];
    // d_in[2] edge_attr, d_in[3] edge_weight: unused by the reference
    const float* Wl0 = (const float*)d_in[4];
    const float* bl0 = (const float*)d_in[5];
    const float* Wr0 = (const float*)d_in[6];
    const float* Ws0 = (const float*)d_in[7];
    const float* bs0 = (const float*)d_in[8];
    const float* Wl1 = (const float*)d_in[9];
    const float* bl1 = (const float*)d_in[10];
    const float* Wr1 = (const float*)d_in[11];
    const float* Ws1 = (const float*)d_in[12];
    const float* bs1 = (const float*)d_in[13];
    const float* Wl2 = (const float*)d_in[14];
    const float* bl2 = (const float*)d_in[15];
    const float* Wr2 = (const float*)d_in[16];
    const float* Ws2 = (const float*)d_in[17];
    const float* bs2 = (const float*)d_in[18];
    float* out = (float*)d_out;

    // dtype probe + fold weights + degree counts (once)
    detect_kernel<<<1, 32>>>((const long long*)ei);
    prep_kernel<<<160, 256>>>(Wr0, Ws0, Wr1, Ws1, Wr2, Ws2,
                              bl0, bs0, bl1, bs1, bl2, bs2);
    zero_cnt_kernel<<<(NN + 255) / 256, 256>>>();
    count_kernel<<<(EE + 255) / 256, 256>>>(ei);
    inv_kernel<<<(NN + 255) / 256, 256>>>();

    const int zeroBlocks    = (NN * DD / 4) / 256;       // exact: 6250
    const int scatterBlocks = (EE * 128) / 256;          // 400000, exact
    const int gemmBlocks    = (NN + 127) / 128;          // 391

    // Layer 0: x -> g_h0
    zero_agg_kernel<<<zeroBlocks, 256>>>();
    scatter_kernel<0><<<scatterBlocks, 256>>>(x, ei);
    gemm_kernel<128, 0, 1, 1><<<gemmBlocks, 256>>>(x, Wl0, 0, 0, nullptr);

    // Layer 1: g_h0 -> g_h1
    zero_agg_kernel<<<zeroBlocks, 256>>>();
    scatter_kernel<1><<<scatterBlocks, 256>>>(nullptr, ei);
    gemm_kernel<128, 1, 2, 1><<<gemmBlocks, 256>>>(nullptr, Wl1, DD * DD, DD, nullptr);

    // Layer 2: g_h1 -> out (no relu)
    zero_agg_kernel<<<zeroBlocks, 256>>>();
    scatter_kernel<2><<<scatterBlocks, 256>>>(nullptr, ei);
    gemm_kernel<64, 2, 0, 0><<<gemmBlocks, 256>>>(nullptr, Wl2, 2 * DD * DD, 2 * DD, out);
}

// round 6
// speedup vs baseline: 1.6087x; 1.6087x over previous
#include <cuda_runtime.h>

#define NN 50000
#define DD 128
#define EE 800000

// Scratch (device globals — no allocation allowed)
__device__ __align__(256) float g_ya[NN * DD];     // x @ Wl
__device__ __align__(256) float g_yb[NN * DD];     // x @ (Wr+Ws)
__device__ __align__(256) float g_h0[NN * DD];
__device__ __align__(256) float g_h1[NN * DD];
__device__ __align__(256) float g_inv[NN];
__device__ __align__(256) int   g_cnt[NN];
__device__ __align__(256) int   g_rowptr[NN];
__device__ __align__(256) int   g_fill[NN];
__device__ __align__(256) int   g_src[EE];
__device__ __align__(256) int   g_dst[EE];
__device__ __align__(256) int   g_csrc[EE];
__device__ __align__(256) float g_wsum[DD * DD * 2 + DD * 64];  // folded Wr+Ws per layer
__device__ __align__(256) float g_bsum[DD + DD + 64];           // folded bl+bs per layer
__device__ int g_is32;   // 1 if edge_index is int32, 0 if int64

// ---------------------------------------------------------------------------
// Detect edge_index dtype: int32 data read as int64 gives out-of-range values.
// ---------------------------------------------------------------------------
__global__ void detect_kernel(const long long* __restrict__ ei) {
    if (blockIdx.x == 0 && threadIdx.x == 0) {
        int is32 = 0;
        for (int i = 0; i < 64; ++i) {
            long long v = ei[i];
            if (v < 0 || v >= NN) { is32 = 1; break; }
        }
        g_is32 = is32;
    }
}

// Convert edges to int32 arrays (once)
__global__ void convert_kernel(const void* __restrict__ ei) {
    int e = blockIdx.x * blockDim.x + threadIdx.x;
    if (e >= EE) return;
    if (g_is32) {
        const int* p = (const int*)ei;
        g_src[e] = p[e];
        g_dst[e] = p[EE + e];
    } else {
        const long long* p = (const long long*)ei;
        g_src[e] = (int)p[e];
        g_dst[e] = (int)p[EE + e];
    }
}

// ---------------------------------------------------------------------------
// Prep: fold Wr+Ws and bl+bs for all 3 layers
// ---------------------------------------------------------------------------
__global__ void prep_kernel(const float* __restrict__ Wr0, const float* __restrict__ Ws0,
                            const float* __restrict__ Wr1, const float* __restrict__ Ws1,
                            const float* __restrict__ Wr2, const float* __restrict__ Ws2,
                            const float* __restrict__ bl0, const float* __restrict__ bs0,
                            const float* __restrict__ bl1, const float* __restrict__ bs1,
                            const float* __restrict__ bl2, const float* __restrict__ bs2) {
    int t = blockIdx.x * blockDim.x + threadIdx.x;
    const int n0 = DD * DD;              // 16384
    if (t < n0)                  g_wsum[t] = Wr0[t] + Ws0[t];
    else if (t < 2 * n0)         g_wsum[t] = Wr1[t - n0] + Ws1[t - n0];
    else if (t < 2 * n0 + DD*64) g_wsum[t] = Wr2[t - 2 * n0] + Ws2[t - 2 * n0];

    if (t < DD)                  g_bsum[t] = bl0[t] + bs0[t];
    else if (t < 2 * DD)         g_bsum[t] = bl1[t - DD] + bs1[t - DD];
    else if (t < 2 * DD + 64)    g_bsum[t] = bl2[t - 2 * DD] + bs2[t - 2 * DD];
}

__global__ void zero_cnt_kernel() {
    int t = blockIdx.x * blockDim.x + threadIdx.x;
    if (t < NN) g_cnt[t] = 0;
}

__global__ void count_kernel() {
    int e = blockIdx.x * blockDim.x + threadIdx.x;
    if (e < EE) atomicAdd(&g_cnt[g_dst[e]], 1);
}

// Single-block exclusive scan over g_cnt -> g_rowptr, g_fill; also g_inv.
__global__ void scan_kernel() {
    const int T = 1024;
    __shared__ int ssum[T];
    int t = threadIdx.x;
    const int CH = (NN + T - 1) / T;          // 49
    int base = t * CH;
    int s = 0;
    for (int i = 0; i < CH; ++i) {
        int idx = base + i;
        if (idx < NN) s += g_cnt[idx];
    }
    ssum[t] = s;
    __syncthreads();
    for (int off = 1; off < T; off <<= 1) {
        int v = (t >= off) ? ssum[t - off] : 0;
        __syncthreads();
        ssum[t] += v;
        __syncthreads();
    }
    int run = (t == 0) ? 0 : ssum[t - 1];
    for (int i = 0; i < CH; ++i) {
        int idx = base + i;
        if (idx < NN) {
            g_rowptr[idx] = run;
            g_fill[idx]   = run;
            g_inv[idx]    = 1.0f / fmaxf((float)g_cnt[idx], 1.0f);
            run += g_cnt[idx];
        }
    }
}

__global__ void fill_kernel() {
    int e = blockIdx.x * blockDim.x + threadIdx.x;
    if (e >= EE) return;
    int pos = atomicAdd(&g_fill[g_dst[e]], 1);
    g_csrc[pos] = g_src[e];
}

// ---------------------------------------------------------------------------
// GEMM: C = A @ B (no epilogue). blockIdx.y selects (B, C):
//   y=0: B = Wl (external),  C = g_ya
//   y=1: B = g_wsum + woff,  C = g_yb
// BM=128, BN = DO, BK=16, 256 threads, 8xTN register tiles.
// SRC selector for A: 0 = external (x), 1 = g_h0, 2 = g_h1
// ---------------------------------------------------------------------------
template<int BN, int SRC>
__global__ void gemm_kernel(const float* __restrict__ Ax_ext,
                            const float* __restrict__ Wl_ext,
                            int woff) {
    constexpr int TN = BN / 16;          // 8 for BN=128, 4 for BN=64
    __shared__ float As[16][132];        // [k][m], padded
    __shared__ float Bs[16][BN];         // [k][n]

    const float* A = (SRC == 0) ? Ax_ext : (SRC == 1) ? g_h0 : g_h1;
    const float* B = (blockIdx.y == 0) ? Wl_ext : (g_wsum + woff);
    float*       C = (blockIdx.y == 0) ? g_ya : g_yb;

    int t  = threadIdx.x;
    int tx = t & 15;
    int ty = t >> 4;
    int row0 = blockIdx.x * 128;

    float acc[8][TN];
    #pragma unroll
    for (int i = 0; i < 8; i++)
        #pragma unroll
        for (int j = 0; j < TN; j++) acc[i][j] = 0.f;

    #pragma unroll 1
    for (int k0 = 0; k0 < 128; k0 += 16) {
        // --- load A tile (128 rows x 16 k), transposed into As[k][m]
        #pragma unroll
        for (int i = 0; i < 2; ++i) {
            int idx = t + i * 256;           // 0..511
            int r   = idx >> 2;              // 0..127
            int kq  = idx & 3;               // 0..3
            int grow = row0 + r;
            float4 v = make_float4(0.f, 0.f, 0.f, 0.f);
            if (grow < NN)
                v = *(const float4*)(A + (size_t)grow * DD + k0 + kq * 4);
            As[kq * 4 + 0][r] = v.x;
            As[kq * 4 + 1][r] = v.y;
            As[kq * 4 + 2][r] = v.z;
            As[kq * 4 + 3][r] = v.w;
        }
        // --- load B tile (16 k x BN cols)
        #pragma unroll
        for (int i = 0; i < (16 * BN) / (256 * 4); ++i) {
            int idx = t + i * 256;           // float4 index
            int r   = idx / (BN / 4);
            int jq  = idx % (BN / 4);
            float4 v = *(const float4*)(B + (k0 + r) * BN + jq * 4);
            *(float4*)&Bs[r][jq * 4] = v;
        }
        __syncthreads();
        // --- compute
        #pragma unroll
        for (int k = 0; k < 16; ++k) {
            float a[8], b[TN];
            *(float4*)&a[0] = *(float4*)&As[k][ty * 8];
            *(float4*)&a[4] = *(float4*)&As[k][ty * 8 + 4];
            *(float4*)&b[0] = *(float4*)&Bs[k][tx * TN];
            if (TN == 8) *(float4*)&b[4] = *(float4*)&Bs[k][tx * TN + 4];
            #pragma unroll
            for (int i = 0; i < 8; i++)
                #pragma unroll
                for (int j = 0; j < TN; j++)
                    acc[i][j] += a[i] * b[j];
        }
        __syncthreads();
    }

    // --- store (raw; bias/relu applied in aggregation)
    #pragma unroll
    for (int i = 0; i < 8; i++) {
        int grow = row0 + ty * 8 + i;
        if (grow < NN) {
            #pragma unroll
            for (int j = 0; j < TN; j += 4) {
                float4 v;
                v.x = acc[i][j + 0]; v.y = acc[i][j + 1];
                v.z = acc[i][j + 2]; v.w = acc[i][j + 3];
                *(float4*)(C + (size_t)grow * BN + tx * TN + j) = v;
            }
        }
    }
}

// ---------------------------------------------------------------------------
// Aggregation: one warp per node.
//   h[n] = relu( mean_{e: dst=n}(ya[src_e]) + yb[n] + bias )
// DO=128 -> float4 per lane; DO=64 -> float2 per lane.
// DST selector: 0 = external (out), 1 = g_h0, 2 = g_h1
// ---------------------------------------------------------------------------
template<int DO, int DST, int RELU>
__global__ void agg_kernel(float* __restrict__ out_ext, int boff) {
    int gt = blockIdx.x * blockDim.x + threadIdx.x;
    int node = gt >> 5;
    int lane = gt & 31;
    if (node >= NN) return;
    float* out = (DST == 0) ? out_ext : (DST == 1) ? g_h0 : g_h1;
    const float* bias = g_bsum + boff;

    int start = g_rowptr[node];
    int deg   = g_cnt[node];
    float inv = g_inv[node];

    if (DO == 128) {
        float4 acc = make_float4(0.f, 0.f, 0.f, 0.f);
        for (int i = 0; i < deg; ++i) {
            int src = g_csrc[start + i];
            float4 v = *(const float4*)(g_ya + (size_t)src * 128 + lane * 4);
            acc.x += v.x; acc.y += v.y; acc.z += v.z; acc.w += v.w;
        }
        float4 yb = *(const float4*)(g_yb + (size_t)node * 128 + lane * 4);
        float4 r;
        r.x = acc.x * inv + yb.x + bias[lane * 4 + 0];
        r.y = acc.y * inv + yb.y + bias[lane * 4 + 1];
        r.z = acc.z * inv + yb.z + bias[lane * 4 + 2];
        r.w = acc.w * inv + yb.w + bias[lane * 4 + 3];
        if (RELU) {
            r.x = fmaxf(r.x, 0.f); r.y = fmaxf(r.y, 0.f);
            r.z = fmaxf(r.z, 0.f); r.w = fmaxf(r.w, 0.f);
        }
        *(float4*)(out + (size_t)node * 128 + lane * 4) = r;
    } else {
        float2 acc = make_float2(0.f, 0.f);
        for (int i = 0; i < deg; ++i) {
            int src = g_csrc[start + i];
            float2 v = *(const float2*)(g_ya + (size_t)src * 64 + lane * 2);
            acc.x += v.x; acc.y += v.y;
        }
        float2 yb = *(const float2*)(g_yb + (size_t)node * 64 + lane * 2);
        float2 r;
        r.x = acc.x * inv + yb.x + bias[lane * 2 + 0];
        r.y = acc.y * inv + yb.y + bias[lane * 2 + 1];
        if (RELU) {
            r.x = fmaxf(r.x, 0.f); r.y = fmaxf(r.y, 0.f);
        }
        *(float2*)(out + (size_t)node * 64 + lane * 2) = r;
    }
}

// ---------------------------------------------------------------------------
extern "C" void kernel_launch(void* const* d_in, const int* in_sizes, int n_in,
                              void* d_out, int out_size) {
    const float* x  = (const float*)d_in[0];
    const void*  ei = d_in[1];
    // d_in[2] edge_attr, d_in[3] edge_weight: unused by the reference
    const float* Wl0 = (const float*)d_in[4];
    const float* bl0 = (const float*)d_in[5];
    const float* Wr0 = (const float*)d_in[6];
    const float* Ws0 = (const float*)d_in[7];
    const float* bs0 = (const float*)d_in[8];
    const float* Wl1 = (const float*)d_in[9];
    const float* bl1 = (const float*)d_in[10];
    const float* Wr1 = (const float*)d_in[11];
    const float* Ws1 = (const float*)d_in[12];
    const float* bs1 = (const float*)d_in[13];
    const float* Wl2 = (const float*)d_in[14];
    const float* bl2 = (const float*)d_in[15];
    const float* Wr2 = (const float*)d_in[16];
    const float* Ws2 = (const float*)d_in[17];
    const float* bs2 = (const float*)d_in[18];
    float* out = (float*)d_out;

    const int eBlocks = (EE + 255) / 256;

    // One-time prep: dtype probe, edge convert, weight fold, CSR build
    detect_kernel<<<1, 32>>>((const long long*)ei);
    convert_kernel<<<eBlocks, 256>>>(ei);
    prep_kernel<<<160, 256>>>(Wr0, Ws0, Wr1, Ws1, Wr2, Ws2,
                              bl0, bs0, bl1, bs1, bl2, bs2);
    zero_cnt_kernel<<<(NN + 255) / 256, 256>>>();
    count_kernel<<<eBlocks, 256>>>();
    scan_kernel<<<1, 1024>>>();
    fill_kernel<<<eBlocks, 256>>>();

    const dim3 gemmGrid((NN + 127) / 128, 2);   // (391, 2)
    const int aggBlocks = (NN * 32 + 255) / 256; // 6250

    // Layer 0: x -> g_h0
    gemm_kernel<128, 0><<<gemmGrid, 256>>>(x, Wl0, 0);
    agg_kernel<128, 1, 1><<<aggBlocks, 256>>>(nullptr, 0);

    // Layer 1: g_h0 -> g_h1
    gemm_kernel<128, 1><<<gemmGrid, 256>>>(nullptr, Wl1, DD * DD);
    agg_kernel<128, 2, 1><<<aggBlocks, 256>>>(nullptr, DD);

    // Layer 2: g_h1 -> out (no relu)
    gemm_kernel<64, 2><<<gemmGrid, 256>>>(nullptr, Wl2, 2 * DD * DD);
    agg_kernel<64, 0, 0><<<aggBlocks, 256>>>(out, 2 * DD);
}

// round 8
// speedup vs baseline: 2.2605x; 1.4051x over previous
#include <cuda_runtime.h>
#include <cuda_bf16.h>
#include <cstdint>

#define NN 50000
#define DD 128
#define EE 800000

// ---------------------------------------------------------------------------
// Scratch (device globals — no allocation allowed)
// ---------------------------------------------------------------------------
__device__ __align__(256) float g_ya[NN * DD];     // A @ Wl
__device__ __align__(256) float g_yb[NN * DD];     // A @ (Wr+Ws)
__device__ __align__(256) float g_h0[NN * DD];
__device__ __align__(256) float g_h1[NN * DD];
__device__ __align__(256) float g_inv[NN];
__device__ __align__(256) int   g_cnt[NN];
__device__ __align__(256) int   g_rowptr[NN];
__device__ __align__(256) int   g_fill[NN];
__device__ __align__(256) int   g_src[EE];
__device__ __align__(256) int   g_dst[EE];
__device__ __align__(256) int   g_csrc[EE];
// Transposed bf16 hi/lo weight images [n][k], per layer:
// L0 @0: hi 64KB + lo 64KB; L1 @131072: same; L2 @262144: hi 32KB + lo 32KB
__device__ __align__(1024) unsigned char g_wbf[327680];
__device__ __align__(256) float g_bsum[DD + DD + 64];
__device__ int g_is32;

// ---------------------------------------------------------------------------
// Edge dtype probe + conversion to int32 arrays
// ---------------------------------------------------------------------------
__global__ void detect_kernel(const long long* __restrict__ ei) {
    if (blockIdx.x == 0 && threadIdx.x == 0) {
        int is32 = 0;
        for (int i = 0; i < 64; ++i) {
            long long v = ei[i];
            if (v < 0 || v >= NN) { is32 = 1; break; }
        }
        g_is32 = is32;
    }
}
__global__ void convert_kernel(const void* __restrict__ ei) {
    int e = blockIdx.x * blockDim.x + threadIdx.x;
    if (e >= EE) return;
    if (g_is32) {
        const int* p = (const int*)ei;
        g_src[e] = p[e]; g_dst[e] = p[EE + e];
    } else {
        const long long* p = (const long long*)ei;
        g_src[e] = (int)p[e]; g_dst[e] = (int)p[EE + e];
    }
}

// ---------------------------------------------------------------------------
// Weight prep: build transposed [n][k] bf16 hi/lo images of [Wl | Wr+Ws].
// Layer 0/1: W=256 (n<128: Wl col n; n>=128: Wr+Ws col n-128)
// Layer 2:   W=128 (n<64: Wl; n>=64: Wr+Ws), dout=64
// ---------------------------------------------------------------------------
__global__ void prepb_kernel(const float* __restrict__ Wl0, const float* __restrict__ Wr0, const float* __restrict__ Ws0,
                             const float* __restrict__ Wl1, const float* __restrict__ Wr1, const float* __restrict__ Ws1,
                             const float* __restrict__ Wl2, const float* __restrict__ Wr2, const float* __restrict__ Ws2) {
    int t = blockIdx.x * blockDim.x + threadIdx.x;
    int dout, n, k; size_t base, hsize;
    const float *Wl, *Wr, *Ws;
    if (t < 32768)       { dout = 128; base = 0;      hsize = 65536; int u = t;         n = u >> 7; k = u & 127; Wl = Wl0; Wr = Wr0; Ws = Ws0; }
    else if (t < 65536)  { dout = 128; base = 131072; hsize = 65536; int u = t - 32768; n = u >> 7; k = u & 127; Wl = Wl1; Wr = Wr1; Ws = Ws1; }
    else if (t < 81920)  { dout = 64;  base = 262144; hsize = 32768; int u = t - 65536; n = u >> 7; k = u & 127; Wl = Wl2; Wr = Wr2; Ws = Ws2; }
    else return;
    float val = (n < dout) ? Wl[k * dout + n]
                           : (Wr[k * dout + (n - dout)] + Ws[k * dout + (n - dout)]);
    __nv_bfloat16 hi = __float2bfloat16(val);
    __nv_bfloat16 lo = __float2bfloat16(val - __bfloat162float(hi));
    size_t off = (size_t)n * 256 + (size_t)k * 2;      // 256B rows (128 bf16)
    *(__nv_bfloat16*)(g_wbf + base + off)         = hi;
    *(__nv_bfloat16*)(g_wbf + base + hsize + off) = lo;
}

__global__ void prep_bias_kernel(const float* __restrict__ bl0, const float* __restrict__ bs0,
                                 const float* __restrict__ bl1, const float* __restrict__ bs1,
                                 const float* __restrict__ bl2, const float* __restrict__ bs2) {
    int t = threadIdx.x;
    if (t < DD)               g_bsum[t] = bl0[t] + bs0[t];
    else if (t < 2 * DD)      g_bsum[t] = bl1[t - DD] + bs1[t - DD];
    else if (t < 2 * DD + 64) g_bsum[t] = bl2[t - 2 * DD] + bs2[t - 2 * DD];
}

// ---------------------------------------------------------------------------
// CSR build
// ---------------------------------------------------------------------------
__global__ void zero_cnt_kernel() {
    int t = blockIdx.x * blockDim.x + threadIdx.x;
    if (t < NN) g_cnt[t] = 0;
}
__global__ void count_kernel() {
    int e = blockIdx.x * blockDim.x + threadIdx.x;
    if (e < EE) atomicAdd(&g_cnt[g_dst[e]], 1);
}
__global__ void scan_kernel() {
    const int T = 1024;
    __shared__ int ssum[T];
    int t = threadIdx.x;
    const int CH = (NN + T - 1) / T;
    int base = t * CH, s = 0;
    for (int i = 0; i < CH; ++i) { int idx = base + i; if (idx < NN) s += g_cnt[idx]; }
    ssum[t] = s;
    __syncthreads();
    for (int off = 1; off < T; off <<= 1) {
        int v = (t >= off) ? ssum[t - off] : 0;
        __syncthreads();
        ssum[t] += v;
        __syncthreads();
    }
    int run = (t == 0) ? 0 : ssum[t - 1];
    for (int i = 0; i < CH; ++i) {
        int idx = base + i;
        if (idx < NN) {
            g_rowptr[idx] = run; g_fill[idx] = run;
            g_inv[idx] = 1.0f / fmaxf((float)g_cnt[idx], 1.0f);
            run += g_cnt[idx];
        }
    }
}
__global__ void fill_kernel() {
    int e = blockIdx.x * blockDim.x + threadIdx.x;
    if (e >= EE) return;
    int pos = atomicAdd(&g_fill[g_dst[e]], 1);
    g_csrc[pos] = g_src[e];
}

// ---------------------------------------------------------------------------
// mma.sync m16n8k16 bf16 (baseline PTX, works on plain sm_103)
// ---------------------------------------------------------------------------
__device__ __forceinline__ void mma_16816(float* c, const uint32_t* a, const uint32_t* b) {
    asm volatile("mma.sync.aligned.m16n8k16.row.col.f32.bf16.bf16.f32 "
                 "{%0,%1,%2,%3}, {%4,%5,%6,%7}, {%8,%9}, {%0,%1,%2,%3};"
                 : "+f"(c[0]), "+f"(c[1]), "+f"(c[2]), "+f"(c[3])
                 : "r"(a[0]), "r"(a[1]), "r"(a[2]), "r"(a[3]), "r"(b[0]), "r"(b[1]));
}

// ---------------------------------------------------------------------------
// Tensor-core GEMM via split-bf16 3-MMA:
//   [g_ya | g_yb] = A @ [Wl | Wr+Ws]
// CTA: 128 rows x W cols, in W/128 passes of 128 cols.
// 8 warps (4 m x 2 n); warp tile per pass: 32(m) x 64(n).
// SMEM (padded row stride 136 bf16 = 272B, conflict-free fragment loads):
//   A_hi 34816 | A_lo 34816 | B_hi W*272 | B_lo W*272
// ---------------------------------------------------------------------------
template<int W, int DOUT, int SRC>
__global__ void __launch_bounds__(256, 1)
tc_gemm_kernel(const float* __restrict__ Ax_ext, int layerOff) {
    constexpr int SA = 136;                  // smem row stride in bf16
    constexpr int A_LO = 34816;              // byte offsets
    constexpr int B_HI = 69632;
    constexpr int B_LO = 69632 + W * 272;
    constexpr int NPASS = W / 128;

    extern __shared__ char smem[];
    int tid = threadIdx.x, wid = tid >> 5, lane = tid & 31;
    int wm = wid >> 1, wn = wid & 1;
    int gid = lane >> 2, tig = lane & 3;
    int row0 = blockIdx.x * 128;
    const float* A = (SRC == 0) ? Ax_ext : (SRC == 1) ? g_h0 : g_h1;

    // --- load A (128 x 128 f32), split to bf16 hi/lo, store padded
    #pragma unroll
    for (int i = 0; i < 16; ++i) {
        int f = tid + i * 256;               // 0..4095
        int r = f >> 5;                      // row
        int k = (f & 31) * 4;                // k start
        int grow = row0 + r;
        float4 v = make_float4(0.f, 0.f, 0.f, 0.f);
        if (grow < NN) v = *(const float4*)(A + (size_t)grow * DD + k);
        __nv_bfloat162 h0, h1, l0, l1;
        h0.x = __float2bfloat16(v.x); h0.y = __float2bfloat16(v.y);
        h1.x = __float2bfloat16(v.z); h1.y = __float2bfloat16(v.w);
        l0.x = __float2bfloat16(v.x - __bfloat162float(h0.x));
        l0.y = __float2bfloat16(v.y - __bfloat162float(h0.y));
        l1.x = __float2bfloat16(v.z - __bfloat162float(h1.x));
        l1.y = __float2bfloat16(v.w - __bfloat162float(h1.y));
        size_t boff = (size_t)(r * SA + k) * 2;
        *(__nv_bfloat162*)(smem + boff)            = h0;
        *(__nv_bfloat162*)(smem + boff + 4)        = h1;
        *(__nv_bfloat162*)(smem + A_LO + boff)     = l0;
        *(__nv_bfloat162*)(smem + A_LO + boff + 4) = l1;
    }

    // --- copy B hi/lo images (256B rows) into padded smem (272B rows)
    {
        constexpr int CH = W * 16;           // 16B chunks per image
        const char* srcH = (const char*)g_wbf + layerOff;
        const char* srcL = srcH + W * 256;
        #pragma unroll
        for (int i = 0; i < CH / 256; ++i) {
            int c = tid + i * 256;
            int n = c >> 4, pos = c & 15;
            size_t doff = (size_t)n * 272 + pos * 16;
            *(float4*)(smem + B_HI + doff) = *(const float4*)(srcH + c * 16);
            *(float4*)(smem + B_LO + doff) = *(const float4*)(srcL + c * 16);
        }
    }
    __syncthreads();

    #pragma unroll
    for (int pass = 0; pass < NPASS; ++pass) {
        float acc[2][8][4];
        #pragma unroll
        for (int mt = 0; mt < 2; ++mt)
            #pragma unroll
            for (int nt = 0; nt < 8; ++nt)
                #pragma unroll
                for (int j = 0; j < 4; ++j) acc[mt][nt][j] = 0.f;

        #pragma unroll 1
        for (int k0 = 0; k0 < 128; k0 += 16) {
            uint32_t ah[2][4], al[2][4];
            #pragma unroll
            for (int mt = 0; mt < 2; ++mt) {
                int r = wm * 32 + mt * 16 + gid;
                size_t o00 = (size_t)(r * SA + k0 + 2 * tig) * 2;
                size_t o10 = o00 + 8 * SA * 2;
                ah[mt][0] = *(const uint32_t*)(smem + o00);
                ah[mt][1] = *(const uint32_t*)(smem + o10);
                ah[mt][2] = *(const uint32_t*)(smem + o00 + 16);
                ah[mt][3] = *(const uint32_t*)(smem + o10 + 16);
                al[mt][0] = *(const uint32_t*)(smem + A_LO + o00);
                al[mt][1] = *(const uint32_t*)(smem + A_LO + o10);
                al[mt][2] = *(const uint32_t*)(smem + A_LO + o00 + 16);
                al[mt][3] = *(const uint32_t*)(smem + A_LO + o10 + 16);
            }
            #pragma unroll
            for (int nt = 0; nt < 8; ++nt) {
                int n = pass * 128 + wn * 64 + nt * 8 + gid;
                size_t bo = (size_t)(n * SA + k0 + 2 * tig) * 2;
                uint32_t bh[2], bl[2];
                bh[0] = *(const uint32_t*)(smem + B_HI + bo);
                bh[1] = *(const uint32_t*)(smem + B_HI + bo + 16);
                bl[0] = *(const uint32_t*)(smem + B_LO + bo);
                bl[1] = *(const uint32_t*)(smem + B_LO + bo + 16);
                #pragma unroll
                for (int mt = 0; mt < 2; ++mt) {
                    mma_16816(acc[mt][nt], ah[mt], bh);
                    mma_16816(acc[mt][nt], ah[mt], bl);
                    mma_16816(acc[mt][nt], al[mt], bh);
                }
            }
        }

        // --- store pass results to g_ya / g_yb
        #pragma unroll
        for (int mt = 0; mt < 2; ++mt) {
            int r0 = row0 + wm * 32 + mt * 16 + gid;
            #pragma unroll
            for (int nt = 0; nt < 8; ++nt) {
                int nglob = pass * 128 + wn * 64 + nt * 8 + 2 * tig;
                float* dst = (nglob < DOUT) ? g_ya : g_yb;
                int col = (nglob < DOUT) ? nglob : nglob - DOUT;
                if (r0 < NN) {
                    float2 v0 = make_float2(acc[mt][nt][0], acc[mt][nt][1]);
                    *(float2*)(dst + (size_t)r0 * DOUT + col) = v0;
                }
                if (r0 + 8 < NN) {
                    float2 v1 = make_float2(acc[mt][nt][2], acc[mt][nt][3]);
                    *(float2*)(dst + (size_t)(r0 + 8) * DOUT + col) = v1;
                }
            }
        }
    }
}

// ---------------------------------------------------------------------------
// Aggregation: one warp per node.
//   h[n] = relu( mean_{e: dst=n}(ya[src_e]) + yb[n] + bias )
// ---------------------------------------------------------------------------
template<int DO, int DST, int RELU>
__global__ void agg_kernel(float* __restrict__ out_ext, int boff) {
    int gt = blockIdx.x * blockDim.x + threadIdx.x;
    int node = gt >> 5;
    int lane = gt & 31;
    if (node >= NN) return;
    float* out = (DST == 0) ? out_ext : (DST == 1) ? g_h0 : g_h1;
    const float* bias = g_bsum + boff;

    int start = g_rowptr[node];
    int deg   = g_cnt[node];
    float inv = g_inv[node];

    if (DO == 128) {
        float4 acc = make_float4(0.f, 0.f, 0.f, 0.f);
        for (int i = 0; i < deg; ++i) {
            int src = g_csrc[start + i];
            float4 v = *(const float4*)(g_ya + (size_t)src * 128 + lane * 4);
            acc.x += v.x; acc.y += v.y; acc.z += v.z; acc.w += v.w;
        }
        float4 yb = *(const float4*)(g_yb + (size_t)node * 128 + lane * 4);
        float4 r;
        r.x = acc.x * inv + yb.x + bias[lane * 4 + 0];
        r.y = acc.y * inv + yb.y + bias[lane * 4 + 1];
        r.z = acc.z * inv + yb.z + bias[lane * 4 + 2];
        r.w = acc.w * inv + yb.w + bias[lane * 4 + 3];
        if (RELU) {
            r.x = fmaxf(r.x, 0.f); r.y = fmaxf(r.y, 0.f);
            r.z = fmaxf(r.z, 0.f); r.w = fmaxf(r.w, 0.f);
        }
        *(float4*)(out + (size_t)node * 128 + lane * 4) = r;
    } else {
        float2 acc = make_float2(0.f, 0.f);
        for (int i = 0; i < deg; ++i) {
            int src = g_csrc[start + i];
            float2 v = *(const float2*)(g_ya + (size_t)src * 64 + lane * 2);
            acc.x += v.x; acc.y += v.y;
        }
        float2 yb = *(const float2*)(g_yb + (size_t)node * 64 + lane * 2);
        float2 r;
        r.x = acc.x * inv + yb.x + bias[lane * 2 + 0];
        r.y = acc.y * inv + yb.y + bias[lane * 2 + 1];
        if (RELU) { r.x = fmaxf(r.x, 0.f); r.y = fmaxf(r.y, 0.f); }
        *(float2*)(out + (size_t)node * 64 + lane * 2) = r;
    }
}

// ---------------------------------------------------------------------------
extern "C" void kernel_launch(void* const* d_in, const int* in_sizes, int n_in,
                              void* d_out, int out_size) {
    const float* x  = (const float*)d_in[0];
    const void*  ei = d_in[1];
    const float* Wl0 = (const float*)d_in[4];
    const float* bl0 = (const float*)d_in[5];
    const float* Wr0 = (const float*)d_in[6];
    const float* Ws0 = (const float*)d_in[7];
    const float* bs0 = (const float*)d_in[8];
    const float* Wl1 = (const float*)d_in[9];
    const float* bl1 = (const float*)d_in[10];
    const float* Wr1 = (const float*)d_in[11];
    const float* Ws1 = (const float*)d_in[12];
    const float* bs1 = (const float*)d_in[13];
    const float* Wl2 = (const float*)d_in[14];
    const float* bl2 = (const float*)d_in[15];
    const float* Wr2 = (const float*)d_in[16];
    const float* Ws2 = (const float*)d_in[17];
    const float* bs2 = (const float*)d_in[18];
    float* out = (float*)d_out;

    const int S256 = 69632 + 2 * 256 * 272;   // 208896
    const int S128 = 69632 + 2 * 128 * 272;   // 139264
    cudaFuncSetAttribute(tc_gemm_kernel<256, 128, 0>, cudaFuncAttributeMaxDynamicSharedMemorySize, S256);
    cudaFuncSetAttribute(tc_gemm_kernel<256, 128, 1>, cudaFuncAttributeMaxDynamicSharedMemorySize, S256);
    cudaFuncSetAttribute(tc_gemm_kernel<128, 64, 2>,  cudaFuncAttributeMaxDynamicSharedMemorySize, S128);

    const int eBlocks    = (EE + 255) / 256;
    const int gemmBlocks = (NN + 127) / 128;     // 391
    const int aggBlocks  = (NN * 32) / 256;      // 6250

    // Prep (order chosen so launch #6 = tc_gemm layer 0 for ncu)
    detect_kernel<<<1, 32>>>((const long long*)ei);                          // 1
    convert_kernel<<<eBlocks, 256>>>(ei);                                    // 2
    prepb_kernel<<<320, 256>>>(Wl0, Wr0, Ws0, Wl1, Wr1, Ws1, Wl2, Wr2, Ws2); // 3
    prep_bias_kernel<<<1, 320>>>(bl0, bs0, bl1, bs1, bl2, bs2);              // 4
    zero_cnt_kernel<<<(NN + 255) / 256, 256>>>();                            // 5

    // Layer 0 GEMM (launch #6 — profiled)
    tc_gemm_kernel<256, 128, 0><<<gemmBlocks, 256, S256>>>(x, 0);            // 6

    // CSR build (needed only by agg)
    count_kernel<<<eBlocks, 256>>>();                                        // 7
    scan_kernel<<<1, 1024>>>();                                              // 8
    fill_kernel<<<eBlocks, 256>>>();                                         // 9

    agg_kernel<128, 1, 1><<<aggBlocks, 256>>>(nullptr, 0);                   // 10

    tc_gemm_kernel<256, 128, 1><<<gemmBlocks, 256, S256>>>(nullptr, 131072); // 11
    agg_kernel<128, 2, 1><<<aggBlocks, 256>>>(nullptr, DD);                  // 12

    tc_gemm_kernel<128, 64, 2><<<gemmBlocks, 256, S128>>>(nullptr, 262144);  // 13
    agg_kernel<64, 0, 0><<<aggBlocks, 256>>>(out, 2 * DD);                   // 14
}

// round 9
// speedup vs baseline: 3.4314x; 1.5180x over previous
#include <cuda_runtime.h>
#include <cuda_bf16.h>
#include <cstdint>

#define NN 50000
#define DD 128
#define EE 800000

// ---------------------------------------------------------------------------
// Scratch (device globals — no allocation allowed)
// ---------------------------------------------------------------------------
__device__ __align__(256) float g_ya[NN * DD];     // A @ Wl
__device__ __align__(256) float g_yb[NN * DD];     // A @ (Wr+Ws)
__device__ __align__(256) float g_h0[NN * DD];
__device__ __align__(256) float g_h1[NN * DD];
__device__ __align__(256) float g_inv[NN];
__device__ __align__(256) int   g_cnt[NN];
__device__ __align__(256) int   g_rowptr[NN];
__device__ __align__(256) int   g_fill[NN];
__device__ __align__(256) int   g_src[EE];
__device__ __align__(256) int   g_dst[EE];
__device__ __align__(256) int   g_csrc[EE];
// Transposed bf16 hi/lo weight images [n][k], per layer:
// L0 @0: hi 64KB + lo 64KB; L1 @131072: same; L2 @262144: hi 32KB + lo 32KB
__device__ __align__(1024) unsigned char g_wbf[327680];
__device__ __align__(256) float g_bsum[DD + DD + 64];
__device__ int g_is32;

// ---------------------------------------------------------------------------
// Edge dtype probe
// ---------------------------------------------------------------------------
__global__ void detect_kernel(const long long* __restrict__ ei) {
    if (blockIdx.x == 0 && threadIdx.x == 0) {
        int is32 = 0;
        for (int i = 0; i < 64; ++i) {
            long long v = ei[i];
            if (v < 0 || v >= NN) { is32 = 1; break; }
        }
        g_is32 = is32;
    }
}

// Convert edges to int32 arrays + histogram destinations (merged)
__global__ void convert_count_kernel(const void* __restrict__ ei) {
    int e = blockIdx.x * blockDim.x + threadIdx.x;
    if (e >= EE) return;
    int s, d;
    if (g_is32) {
        const int* p = (const int*)ei;
        s = p[e]; d = p[EE + e];
    } else {
        const long long* p = (const long long*)ei;
        s = (int)p[e]; d = (int)p[EE + e];
    }
    g_src[e] = s;
    g_dst[e] = d;
    atomicAdd(&g_cnt[d], 1);
}

// ---------------------------------------------------------------------------
// Weight prep (+ bias fold): transposed [n][k] bf16 hi/lo images of [Wl | Wr+Ws]
// ---------------------------------------------------------------------------
__global__ void prepb_kernel(const float* __restrict__ Wl0, const float* __restrict__ Wr0, const float* __restrict__ Ws0,
                             const float* __restrict__ Wl1, const float* __restrict__ Wr1, const float* __restrict__ Ws1,
                             const float* __restrict__ Wl2, const float* __restrict__ Wr2, const float* __restrict__ Ws2,
                             const float* __restrict__ bl0, const float* __restrict__ bs0,
                             const float* __restrict__ bl1, const float* __restrict__ bs1,
                             const float* __restrict__ bl2, const float* __restrict__ bs2) {
    int t = blockIdx.x * blockDim.x + threadIdx.x;
    if (t >= 81920) {
        int b = t - 81920;
        if (b < DD)               g_bsum[b] = bl0[b] + bs0[b];
        else if (b < 2 * DD)      g_bsum[b] = bl1[b - DD] + bs1[b - DD];
        else if (b < 2 * DD + 64) g_bsum[b] = bl2[b - 2 * DD] + bs2[b - 2 * DD];
        return;
    }
    int dout, n, k; size_t base, hsize;
    const float *Wl, *Wr, *Ws;
    if (t < 32768)       { dout = 128; base = 0;      hsize = 65536; int u = t;         n = u >> 7; k = u & 127; Wl = Wl0; Wr = Wr0; Ws = Ws0; }
    else if (t < 65536)  { dout = 128; base = 131072; hsize = 65536; int u = t - 32768; n = u >> 7; k = u & 127; Wl = Wl1; Wr = Wr1; Ws = Ws1; }
    else                 { dout = 64;  base = 262144; hsize = 32768; int u = t - 65536; n = u >> 7; k = u & 127; Wl = Wl2; Wr = Wr2; Ws = Ws2; }
    float val = (n < dout) ? Wl[k * dout + n]
                           : (Wr[k * dout + (n - dout)] + Ws[k * dout + (n - dout)]);
    __nv_bfloat16 hi = __float2bfloat16(val);
    __nv_bfloat16 lo = __float2bfloat16(val - __bfloat162float(hi));
    size_t off = (size_t)n * 256 + (size_t)k * 2;      // 256B rows (128 bf16)
    *(__nv_bfloat16*)(g_wbf + base + off)         = hi;
    *(__nv_bfloat16*)(g_wbf + base + hsize + off) = lo;
}

// ---------------------------------------------------------------------------
// CSR build
// ---------------------------------------------------------------------------
__global__ void zero_cnt_kernel() {
    int t = blockIdx.x * blockDim.x + threadIdx.x;
    if (t < NN) g_cnt[t] = 0;
}
__global__ void scan_kernel() {
    const int T = 1024;
    __shared__ int ssum[T];
    int t = threadIdx.x;
    const int CH = (NN + T - 1) / T;
    int base = t * CH, s = 0;
    for (int i = 0; i < CH; ++i) { int idx = base + i; if (idx < NN) s += g_cnt[idx]; }
    ssum[t] = s;
    __syncthreads();
    for (int off = 1; off < T; off <<= 1) {
        int v = (t >= off) ? ssum[t - off] : 0;
        __syncthreads();
        ssum[t] += v;
        __syncthreads();
    }
    int run = (t == 0) ? 0 : ssum[t - 1];
    for (int i = 0; i < CH; ++i) {
        int idx = base + i;
        if (idx < NN) {
            g_rowptr[idx] = run; g_fill[idx] = run;
            g_inv[idx] = 1.0f / fmaxf((float)g_cnt[idx], 1.0f);
            run += g_cnt[idx];
        }
    }
}
__global__ void fill_kernel() {
    int e = blockIdx.x * blockDim.x + threadIdx.x;
    if (e >= EE) return;
    int pos = atomicAdd(&g_fill[g_dst[e]], 1);
    g_csrc[pos] = g_src[e];
}

// ---------------------------------------------------------------------------
// mma.sync m16n8k16 bf16 (baseline PTX, works on plain sm_103)
// ---------------------------------------------------------------------------
__device__ __forceinline__ void mma_16816(float* c, const uint32_t* a, const uint32_t* b) {
    asm volatile("mma.sync.aligned.m16n8k16.row.col.f32.bf16.bf16.f32 "
                 "{%0,%1,%2,%3}, {%4,%5,%6,%7}, {%8,%9}, {%0,%1,%2,%3};"
                 : "+f"(c[0]), "+f"(c[1]), "+f"(c[2]), "+f"(c[3])
                 : "r"(a[0]), "r"(a[1]), "r"(a[2]), "r"(a[3]), "r"(b[0]), "r"(b[1]));
}

// ---------------------------------------------------------------------------
// Tensor-core GEMM via split-bf16 3-MMA:  [g_ya | g_yb] = A @ [Wl | Wr+Ws]
// 512 threads, 16 warps (4m x 4n), warp tile 32x32 per 128-col pass.
// SMEM padded stride 272B -> conflict-free fragment loads.
// ---------------------------------------------------------------------------
template<int W, int DOUT, int SRC>
__global__ void __launch_bounds__(512, 1)
tc_gemm_kernel(const float* __restrict__ Ax_ext, int layerOff) {
    constexpr int SA = 136;                  // smem row stride in bf16
    constexpr int A_LO = 34816;              // byte offsets
    constexpr int B_HI = 69632;
    constexpr int B_LO = 69632 + W * 272;
    constexpr int NPASS = W / 128;

    extern __shared__ char smem[];
    int tid = threadIdx.x, wid = tid >> 5, lane = tid & 31;
    int wm = wid >> 2, wn = wid & 3;
    int gid = lane >> 2, tig = lane & 3;
    int row0 = blockIdx.x * 128;
    const float* A = (SRC == 0) ? Ax_ext : (SRC == 1) ? g_h0 : g_h1;

    // --- load A (128 x 128 f32), split to bf16 hi/lo, store padded
    #pragma unroll
    for (int i = 0; i < 8; ++i) {
        int f = tid + i * 512;               // 0..4095
        int r = f >> 5;
        int k = (f & 31) * 4;
        int grow = row0 + r;
        float4 v = make_float4(0.f, 0.f, 0.f, 0.f);
        if (grow < NN) v = *(const float4*)(A + (size_t)grow * DD + k);
        __nv_bfloat162 h0, h1, l0, l1;
        h0.x = __float2bfloat16(v.x); h0.y = __float2bfloat16(v.y);
        h1.x = __float2bfloat16(v.z); h1.y = __float2bfloat16(v.w);
        l0.x = __float2bfloat16(v.x - __bfloat162float(h0.x));
        l0.y = __float2bfloat16(v.y - __bfloat162float(h0.y));
        l1.x = __float2bfloat16(v.z - __bfloat162float(h1.x));
        l1.y = __float2bfloat16(v.w - __bfloat162float(h1.y));
        size_t boff = (size_t)(r * SA + k) * 2;
        *(__nv_bfloat162*)(smem + boff)            = h0;
        *(__nv_bfloat162*)(smem + boff + 4)        = h1;
        *(__nv_bfloat162*)(smem + A_LO + boff)     = l0;
        *(__nv_bfloat162*)(smem + A_LO + boff + 4) = l1;
    }

    // --- copy B hi/lo images (256B rows) into padded smem (272B rows)
    {
        constexpr int CH = W * 16;           // 16B chunks per image
        const char* srcH = (const char*)g_wbf + layerOff;
        const char* srcL = srcH + W * 256;
        #pragma unroll
        for (int i = 0; i < CH / 512; ++i) {
            int c = tid + i * 512;
            int n = c >> 4, pos = c & 15;
            size_t doff = (size_t)n * 272 + pos * 16;
            *(float4*)(smem + B_HI + doff) = *(const float4*)(srcH + c * 16);
            *(float4*)(smem + B_LO + doff) = *(const float4*)(srcL + c * 16);
        }
    }
    __syncthreads();

    #pragma unroll
    for (int pass = 0; pass < NPASS; ++pass) {
        float acc[2][4][4];
        #pragma unroll
        for (int mt = 0; mt < 2; ++mt)
            #pragma unroll
            for (int nt = 0; nt < 4; ++nt)
                #pragma unroll
                for (int j = 0; j < 4; ++j) acc[mt][nt][j] = 0.f;

        #pragma unroll 1
        for (int k0 = 0; k0 < 128; k0 += 16) {
            uint32_t ah[2][4], al[2][4];
            #pragma unroll
            for (int mt = 0; mt < 2; ++mt) {
                int r = wm * 32 + mt * 16 + gid;
                size_t o00 = (size_t)(r * SA + k0 + 2 * tig) * 2;
                size_t o10 = o00 + 8 * SA * 2;
                ah[mt][0] = *(const uint32_t*)(smem + o00);
                ah[mt][1] = *(const uint32_t*)(smem + o10);
                ah[mt][2] = *(const uint32_t*)(smem + o00 + 16);
                ah[mt][3] = *(const uint32_t*)(smem + o10 + 16);
                al[mt][0] = *(const uint32_t*)(smem + A_LO + o00);
                al[mt][1] = *(const uint32_t*)(smem + A_LO + o10);
                al[mt][2] = *(const uint32_t*)(smem + A_LO + o00 + 16);
                al[mt][3] = *(const uint32_t*)(smem + A_LO + o10 + 16);
            }
            #pragma unroll
            for (int nt = 0; nt < 4; ++nt) {
                int n = pass * 128 + wn * 32 + nt * 8 + gid;
                size_t bo = (size_t)(n * SA + k0 + 2 * tig) * 2;
                uint32_t bh[2], bl[2];
                bh[0] = *(const uint32_t*)(smem + B_HI + bo);
                bh[1] = *(const uint32_t*)(smem + B_HI + bo + 16);
                bl[0] = *(const uint32_t*)(smem + B_LO + bo);
                bl[1] = *(const uint32_t*)(smem + B_LO + bo + 16);
                #pragma unroll
                for (int mt = 0; mt < 2; ++mt) {
                    mma_16816(acc[mt][nt], ah[mt], bh);
                    mma_16816(acc[mt][nt], ah[mt], bl);
                    mma_16816(acc[mt][nt], al[mt], bh);
                }
            }
        }

        // --- store pass results to g_ya / g_yb
        #pragma unroll
        for (int mt = 0; mt < 2; ++mt) {
            int r0 = row0 + wm * 32 + mt * 16 + gid;
            #pragma unroll
            for (int nt = 0; nt < 4; ++nt) {
                int nglob = pass * 128 + wn * 32 + nt * 8 + 2 * tig;
                float* dst = (nglob < DOUT) ? g_ya : g_yb;
                int col = (nglob < DOUT) ? nglob : nglob - DOUT;
                if (r0 < NN) {
                    float2 v0 = make_float2(acc[mt][nt][0], acc[mt][nt][1]);
                    *(float2*)(dst + (size_t)r0 * DOUT + col) = v0;
                }
                if (r0 + 8 < NN) {
                    float2 v1 = make_float2(acc[mt][nt][2], acc[mt][nt][3]);
                    *(float2*)(dst + (size_t)(r0 + 8) * DOUT + col) = v1;
                }
            }
        }
    }
}

// ---------------------------------------------------------------------------
// Aggregation: one warp per node, edges unrolled x2 (independent accumulators).
//   h[n] = relu( mean_{e: dst=n}(ya[src_e]) + yb[n] + bias )
// ---------------------------------------------------------------------------
template<int DO, int DST, int RELU>
__global__ void agg_kernel(float* __restrict__ out_ext, int boff) {
    int gt = blockIdx.x * blockDim.x + threadIdx.x;
    int node = gt >> 5;
    int lane = gt & 31;
    if (node >= NN) return;
    float* out = (DST == 0) ? out_ext : (DST == 1) ? g_h0 : g_h1;
    const float* bias = g_bsum + boff;

    int start = g_rowptr[node];
    int deg   = g_cnt[node];
    float inv = g_inv[node];

    if (DO == 128) {
        float4 a0 = make_float4(0.f, 0.f, 0.f, 0.f);
        float4 a1 = make_float4(0.f, 0.f, 0.f, 0.f);
        int i = 0;
        for (; i + 1 < deg; i += 2) {
            int s0 = g_csrc[start + i];
            int s1 = g_csrc[start + i + 1];
            float4 v0 = *(const float4*)(g_ya + (size_t)s0 * 128 + lane * 4);
            float4 v1 = *(const float4*)(g_ya + (size_t)s1 * 128 + lane * 4);
            a0.x += v0.x; a0.y += v0.y; a0.z += v0.z; a0.w += v0.w;
            a1.x += v1.x; a1.y += v1.y; a1.z += v1.z; a1.w += v1.w;
        }
        if (i < deg) {
            int s0 = g_csrc[start + i];
            float4 v0 = *(const float4*)(g_ya + (size_t)s0 * 128 + lane * 4);
            a0.x += v0.x; a0.y += v0.y; a0.z += v0.z; a0.w += v0.w;
        }
        a0.x += a1.x; a0.y += a1.y; a0.z += a1.z; a0.w += a1.w;
        float4 yb = *(const float4*)(g_yb + (size_t)node * 128 + lane * 4);
        float4 r;
        r.x = a0.x * inv + yb.x + bias[lane * 4 + 0];
        r.y = a0.y * inv + yb.y + bias[lane * 4 + 1];
        r.z = a0.z * inv + yb.z + bias[lane * 4 + 2];
        r.w = a0.w * inv + yb.w + bias[lane * 4 + 3];
        if (RELU) {
            r.x = fmaxf(r.x, 0.f); r.y = fmaxf(r.y, 0.f);
            r.z = fmaxf(r.z, 0.f); r.w = fmaxf(r.w, 0.f);
        }
        *(float4*)(out + (size_t)node * 128 + lane * 4) = r;
    } else {
        float2 a0 = make_float2(0.f, 0.f);
        float2 a1 = make_float2(0.f, 0.f);
        int i = 0;
        for (; i + 1 < deg; i += 2) {
            int s0 = g_csrc[start + i];
            int s1 = g_csrc[start + i + 1];
            float2 v0 = *(const float2*)(g_ya + (size_t)s0 * 64 + lane * 2);
            float2 v1 = *(const float2*)(g_ya + (size_t)s1 * 64 + lane * 2);
            a0.x += v0.x; a0.y += v0.y;
            a1.x += v1.x; a1.y += v1.y;
        }
        if (i < deg) {
            int s0 = g_csrc[start + i];
            float2 v0 = *(const float2*)(g_ya + (size_t)s0 * 64 + lane * 2);
            a0.x += v0.x; a0.y += v0.y;
        }
        a0.x += a1.x; a0.y += a1.y;
        float2 yb = *(const float2*)(g_yb + (size_t)node * 64 + lane * 2);
        float2 r;
        r.x = a0.x * inv + yb.x + bias[lane * 2 + 0];
        r.y = a0.y * inv + yb.y + bias[lane * 2 + 1];
        if (RELU) { r.x = fmaxf(r.x, 0.f); r.y = fmaxf(r.y, 0.f); }
        *(float2*)(out + (size_t)node * 64 + lane * 2) = r;
    }
}

// ---------------------------------------------------------------------------
extern "C" void kernel_launch(void* const* d_in, const int* in_sizes, int n_in,
                              void* d_out, int out_size) {
    const float* x  = (const float*)d_in[0];
    const void*  ei = d_in[1];
    const float* Wl0 = (const float*)d_in[4];
    const float* bl0 = (const float*)d_in[5];
    const float* Wr0 = (const float*)d_in[6];
    const float* Ws0 = (const float*)d_in[7];
    const float* bs0 = (const float*)d_in[8];
    const float* Wl1 = (const float*)d_in[9];
    const float* bl1 = (const float*)d_in[10];
    const float* Wr1 = (const float*)d_in[11];
    const float* Ws1 = (const float*)d_in[12];
    const float* bs1 = (const float*)d_in[13];
    const float* Wl2 = (const float*)d_in[14];
    const float* bl2 = (const float*)d_in[15];
    const float* Wr2 = (const float*)d_in[16];
    const float* Ws2 = (const float*)d_in[17];
    const float* bs2 = (const float*)d_in[18];
    float* out = (float*)d_out;

    const int S256 = 69632 + 2 * 256 * 272;   // 208896
    const int S128 = 69632 + 2 * 128 * 272;   // 139264
    cudaFuncSetAttribute(tc_gemm_kernel<256, 128, 0>, cudaFuncAttributeMaxDynamicSharedMemorySize, S256);
    cudaFuncSetAttribute(tc_gemm_kernel<256, 128, 1>, cudaFuncAttributeMaxDynamicSharedMemorySize, S256);
    cudaFuncSetAttribute(tc_gemm_kernel<128, 64, 2>,  cudaFuncAttributeMaxDynamicSharedMemorySize, S128);

    const int eBlocks    = (EE + 255) / 256;
    const int gemmBlocks = (NN + 127) / 128;     // 391
    const int aggBlocks  = (NN * 32) / 256;      // 6250

    // Order: tc_gemm L0 is launch #3 (0-based) -> profiled by ncu (-s 5 incl. 2 harness launches)
    prepb_kernel<<<322, 256>>>(Wl0, Wr0, Ws0, Wl1, Wr1, Ws1, Wl2, Wr2, Ws2,
                               bl0, bs0, bl1, bs1, bl2, bs2);               // 0
    zero_cnt_kernel<<<(NN + 255) / 256, 256>>>();                            // 1
    detect_kernel<<<1, 32>>>((const long long*)ei);                          // 2

    tc_gemm_kernel<256, 128, 0><<<gemmBlocks, 512, S256>>>(x, 0);            // 3 (profiled)

    convert_count_kernel<<<eBlocks, 256>>>(ei);                              // 4
    scan_kernel<<<1, 1024>>>();                                              // 5
    fill_kernel<<<eBlocks, 256>>>();                                         // 6

    agg_kernel<128, 1, 1><<<aggBlocks, 256>>>(nullptr, 0);                   // 7

    tc_gemm_kernel<256, 128, 1><<<gemmBlocks, 512, S256>>>(nullptr, 131072); // 8
    agg_kernel<128, 2, 1><<<aggBlocks, 256>>>(nullptr, DD);                  // 9

    tc_gemm_kernel<128, 64, 2><<<gemmBlocks, 512, S128>>>(nullptr, 262144);  // 10
    agg_kernel<64, 0, 0><<<aggBlocks, 256>>>(out, 2 * DD);                   // 11
}

// round 10
// speedup vs baseline: 4.5466x; 1.3250x over previous
#include <cuda_runtime.h>
#include <cuda_bf16.h>
#include <cstdint>

#define NN 50000
#define DD 128
#define EE 800000

// ---------------------------------------------------------------------------
// Scratch (device globals — no allocation allowed)
// ---------------------------------------------------------------------------
__device__ __align__(256) float g_ya[NN * DD];     // A @ Wl
__device__ __align__(256) float g_yb[NN * DD];     // A @ (Wr+Ws)
__device__ __align__(256) float g_h0[NN * DD];
__device__ __align__(256) float g_h1[NN * DD];
__device__ __align__(256) float g_inv[NN];
__device__ __align__(256) int   g_cnt[NN];
__device__ __align__(256) int   g_rowptr[NN];
__device__ __align__(256) int   g_fill[NN];
__device__ __align__(256) int   g_src[EE];
__device__ __align__(256) int   g_dst[EE];
__device__ __align__(256) int   g_csrc[EE];
__device__ __align__(256) int   g_bsum2[256];      // block sums for scan
__device__ __align__(256) int   g_boff[256];       // block offsets for scan
// Fragment-ready bf16 hi/lo weight images per layer:
// L0 @0: hi 64KB + lo 64KB; L1 @131072: same; L2 @262144: hi 32KB + lo 32KB
__device__ __align__(1024) unsigned char g_wbf[327680];
__device__ __align__(256) float g_bsum[DD + DD + 64];
__device__ int g_is32;

// ---------------------------------------------------------------------------
// Edge dtype probe
// ---------------------------------------------------------------------------
__global__ void detect_kernel(const long long* __restrict__ ei) {
    if (blockIdx.x == 0 && threadIdx.x == 0) {
        int is32 = 0;
        for (int i = 0; i < 64; ++i) {
            long long v = ei[i];
            if (v < 0 || v >= NN) { is32 = 1; break; }
        }
        g_is32 = is32;
    }
}

// Convert edges to int32 arrays + histogram destinations (merged)
__global__ void convert_count_kernel(const void* __restrict__ ei) {
    int e = blockIdx.x * blockDim.x + threadIdx.x;
    if (e >= EE) return;
    int s, d;
    if (g_is32) {
        const int* p = (const int*)ei;
        s = p[e]; d = p[EE + e];
    } else {
        const long long* p = (const long long*)ei;
        s = (int)p[e]; d = (int)p[EE + e];
    }
    g_src[e] = s;
    g_dst[e] = d;
    atomicAdd(&g_cnt[d], 1);
}

// ---------------------------------------------------------------------------
// Weight prep (+ bias fold): FRAGMENT-READY bf16 hi/lo images of [Wl | Wr+Ws].
// B fragment layout for mma m16n8k16 (B is [n][k], n-major, K contiguous):
//   tile (nb = n/8, ks = k/16); lane = (n%8)*4 + ((k%16)%8)/2;
//   word = (k%16)/8; half = k%2;  addr = ((nb*8+ks)*32 + lane)*8 + word*4 + half*2
// ---------------------------------------------------------------------------
__global__ void prepb_kernel(const float* __restrict__ Wl0, const float* __restrict__ Wr0, const float* __restrict__ Ws0,
                             const float* __restrict__ Wl1, const float* __restrict__ Wr1, const float* __restrict__ Ws1,
                             const float* __restrict__ Wl2, const float* __restrict__ Wr2, const float* __restrict__ Ws2,
                             const float* __restrict__ bl0, const float* __restrict__ bs0,
                             const float* __restrict__ bl1, const float* __restrict__ bs1,
                             const float* __restrict__ bl2, const float* __restrict__ bs2) {
    int t = blockIdx.x * blockDim.x + threadIdx.x;
    if (t >= 81920) {
        int b = t - 81920;
        if (b < DD)               g_bsum[b] = bl0[b] + bs0[b];
        else if (b < 2 * DD)      g_bsum[b] = bl1[b - DD] + bs1[b - DD];
        else if (b < 2 * DD + 64) g_bsum[b] = bl2[b - 2 * DD] + bs2[b - 2 * DD];
        return;
    }
    int dout, n, k; size_t base, hsize;
    const float *Wl, *Wr, *Ws;
    if (t < 32768)       { dout = 128; base = 0;      hsize = 65536; int u = t;         n = u >> 7; k = u & 127; Wl = Wl0; Wr = Wr0; Ws = Ws0; }
    else if (t < 65536)  { dout = 128; base = 131072; hsize = 65536; int u = t - 32768; n = u >> 7; k = u & 127; Wl = Wl1; Wr = Wr1; Ws = Ws1; }
    else                 { dout = 64;  base = 262144; hsize = 32768; int u = t - 65536; n = u >> 7; k = u & 127; Wl = Wl2; Wr = Wr2; Ws = Ws2; }
    float val = (n < dout) ? Wl[k * dout + n]
                           : (Wr[k * dout + (n - dout)] + Ws[k * dout + (n - dout)]);
    __nv_bfloat16 hi = __float2bfloat16(val);
    __nv_bfloat16 lo = __float2bfloat16(val - __bfloat162float(hi));
    int nb = n >> 3, ks = k >> 4, kin = k & 15;
    int lane = (n & 7) * 4 + ((kin & 7) >> 1);
    int word = kin >> 3, half = kin & 1;
    size_t off = (size_t)(((nb * 8 + ks) * 32 + lane) * 8 + word * 4 + half * 2);
    *(__nv_bfloat16*)(g_wbf + base + off)         = hi;
    *(__nv_bfloat16*)(g_wbf + base + hsize + off) = lo;
}

// ---------------------------------------------------------------------------
// CSR build: zero, count (merged above), 3-stage scan, fill
// ---------------------------------------------------------------------------
__global__ void zero_cnt_kernel() {
    int t = blockIdx.x * blockDim.x + threadIdx.x;
    if (t < NN) g_cnt[t] = 0;
}
// Stage A: per-block sums (196 blocks x 256)
__global__ void scanA_kernel() {
    __shared__ int sh[256];
    int t = threadIdx.x;
    int idx = blockIdx.x * 256 + t;
    sh[t] = (idx < NN) ? g_cnt[idx] : 0;
    __syncthreads();
    for (int off = 128; off > 0; off >>= 1) {
        if (t < off) sh[t] += sh[t + off];
        __syncthreads();
    }
    if (t == 0) g_bsum2[blockIdx.x] = sh[0];
}
// Stage B: exclusive scan of block sums (1 block x 256)
__global__ void scanB_kernel(int nblocks) {
    __shared__ int sh[256];
    int t = threadIdx.x;
    sh[t] = (t < nblocks) ? g_bsum2[t] : 0;
    __syncthreads();
    for (int off = 1; off < 256; off <<= 1) {
        int v = (t >= off) ? sh[t - off] : 0;
        __syncthreads();
        sh[t] += v;
        __syncthreads();
    }
    if (t < nblocks) g_boff[t] = (t == 0) ? 0 : sh[t - 1];
}
// Stage C: local exclusive scan + offset; write rowptr/fill/inv
__global__ void scanC_kernel() {
    __shared__ int sh[256];
    int t = threadIdx.x;
    int idx = blockIdx.x * 256 + t;
    int c = (idx < NN) ? g_cnt[idx] : 0;
    sh[t] = c;
    __syncthreads();
    for (int off = 1; off < 256; off <<= 1) {
        int v = (t >= off) ? sh[t - off] : 0;
        __syncthreads();
        sh[t] += v;
        __syncthreads();
    }
    if (idx < NN) {
        int run = g_boff[blockIdx.x] + sh[t] - c;   // exclusive
        g_rowptr[idx] = run;
        g_fill[idx]   = run;
        g_inv[idx]    = 1.0f / fmaxf((float)c, 1.0f);
    }
}
__global__ void fill_kernel() {
    int e = blockIdx.x * blockDim.x + threadIdx.x;
    if (e >= EE) return;
    int pos = atomicAdd(&g_fill[g_dst[e]], 1);
    g_csrc[pos] = g_src[e];
}

// ---------------------------------------------------------------------------
// mma.sync m16n8k16 bf16 (baseline PTX, works on plain sm_103)
// ---------------------------------------------------------------------------
__device__ __forceinline__ void mma_16816(float* c, const uint32_t* a, const uint32_t* b) {
    asm volatile("mma.sync.aligned.m16n8k16.row.col.f32.bf16.bf16.f32 "
                 "{%0,%1,%2,%3}, {%4,%5,%6,%7}, {%8,%9}, {%0,%1,%2,%3};"
                 : "+f"(c[0]), "+f"(c[1]), "+f"(c[2]), "+f"(c[3])
                 : "r"(a[0]), "r"(a[1]), "r"(a[2]), "r"(a[3]), "r"(b[0]), "r"(b[1]));
}

// ---------------------------------------------------------------------------
// Tensor-core GEMM via split-bf16 3-MMA:  [g_ya | g_yb] = A @ [Wl | Wr+Ws]
// 512 threads, 16 warps (4m x 4n), warp tile 32x32 per 128-col pass.
// FRAGMENT-READY smem: A tile (rb = r/16, ks): lane*16B units holding
// {a0,a1,a2,a3}; B tile (nb, ks): lane*8B holding {b0,b1}. All loads are
// LDS.128 / LDS.64, conflict-free, no padding.
// SMEM map: A_hi [0,32K) | A_lo [32K,64K) | B_hi [64K,64K+W*256) | B_lo after.
// ---------------------------------------------------------------------------
template<int W, int DOUT, int SRC>
__global__ void __launch_bounds__(512, 1)
tc_gemm_kernel(const float* __restrict__ Ax_ext, int layerOff) {
    constexpr int A_LO = 32768;
    constexpr int B_HI = 65536;
    constexpr int BIMG = W * 256;            // bytes per B hi (or lo) image
    constexpr int B_LO = B_HI + BIMG;
    constexpr int NPASS = W / 128;

    extern __shared__ char smem[];
    int tid = threadIdx.x, wid = tid >> 5, lane = tid & 31;
    int wm = wid >> 2, wn = wid & 3;
    int row0 = blockIdx.x * 128;
    const float* A = (SRC == 0) ? Ax_ext : (SRC == 1) ? g_h0 : g_h1;

    // --- load A (128 x 128 f32), split to bf16 hi/lo, store fragment-ready
    #pragma unroll
    for (int i = 0; i < 8; ++i) {
        int f = tid + i * 512;               // 0..4095
        int r = f >> 5;
        int k = (f & 31) * 4;
        int grow = row0 + r;
        float4 v = make_float4(0.f, 0.f, 0.f, 0.f);
        if (grow < NN) v = *(const float4*)(A + (size_t)grow * DD + k);
        uint32_t h0, h1, l0, l1;
        {
            __nv_bfloat162 a, b, c, d;
            a.x = __float2bfloat16(v.x); a.y = __float2bfloat16(v.y);
            b.x = __float2bfloat16(v.z); b.y = __float2bfloat16(v.w);
            c.x = __float2bfloat16(v.x - __bfloat162float(a.x));
            c.y = __float2bfloat16(v.y - __bfloat162float(a.y));
            d.x = __float2bfloat16(v.z - __bfloat162float(b.x));
            d.y = __float2bfloat16(v.w - __bfloat162float(b.y));
            h0 = *(uint32_t*)&a; h1 = *(uint32_t*)&b;
            l0 = *(uint32_t*)&c; l1 = *(uint32_t*)&d;
        }
        int rb = r >> 4, g = r & 15;
        int ks = k >> 4, kin = k & 15;
        int w = (g >> 3) + ((kin >> 3) << 1);
        int ln0 = (g & 7) * 4 + ((kin & 7) >> 1);    // float4 spans 2 lanes
        uint32_t tb = (uint32_t)(((rb * 8 + ks) * 32) * 16 + w * 4);
        *(uint32_t*)(smem + tb + ln0 * 16)            = h0;
        *(uint32_t*)(smem + tb + (ln0 + 1) * 16)      = h1;
        *(uint32_t*)(smem + A_LO + tb + ln0 * 16)     = l0;
        *(uint32_t*)(smem + A_LO + tb + (ln0 + 1) * 16) = l1;
    }

    // --- copy fragment-ready B hi/lo images verbatim
    {
        const float4* src = (const float4*)(g_wbf + layerOff);
        float4* dst = (float4*)(smem + B_HI);
        constexpr int N4 = 2 * BIMG / 16;
        #pragma unroll
        for (int i = 0; i < N4 / 512; ++i) dst[tid + i * 512] = src[tid + i * 512];
    }
    __syncthreads();

    #pragma unroll
    for (int pass = 0; pass < NPASS; ++pass) {
        float acc[2][4][4];
        #pragma unroll
        for (int mt = 0; mt < 2; ++mt)
            #pragma unroll
            for (int nt = 0; nt < 4; ++nt)
                #pragma unroll
                for (int j = 0; j < 4; ++j) acc[mt][nt][j] = 0.f;

        #pragma unroll 2
        for (int ks = 0; ks < 8; ++ks) {
            uint4 ah[2], al[2];
            #pragma unroll
            for (int mt = 0; mt < 2; ++mt) {
                int rb = wm * 2 + mt;
                uint32_t ao = (uint32_t)(((rb * 8 + ks) * 32 + lane) * 16);
                ah[mt] = *(const uint4*)(smem + ao);
                al[mt] = *(const uint4*)(smem + A_LO + ao);
            }
            #pragma unroll
            for (int nt = 0; nt < 4; ++nt) {
                int nb = pass * 16 + wn * 4 + nt;
                uint32_t bo = (uint32_t)(((nb * 8 + ks) * 32 + lane) * 8);
                uint2 bh = *(const uint2*)(smem + B_HI + bo);
                uint2 bl = *(const uint2*)(smem + B_LO + bo);
                #pragma unroll
                for (int mt = 0; mt < 2; ++mt) {
                    mma_16816(acc[mt][nt], (const uint32_t*)&ah[mt], (const uint32_t*)&bh);
                    mma_16816(acc[mt][nt], (const uint32_t*)&ah[mt], (const uint32_t*)&bl);
                    mma_16816(acc[mt][nt], (const uint32_t*)&al[mt], (const uint32_t*)&bh);
                }
            }
        }

        // --- store pass results to g_ya / g_yb
        int gid = lane >> 2, tig = lane & 3;
        #pragma unroll
        for (int mt = 0; mt < 2; ++mt) {
            int r0 = row0 + wm * 32 + mt * 16 + gid;
            #pragma unroll
            for (int nt = 0; nt < 4; ++nt) {
                int nglob = pass * 128 + wn * 32 + nt * 8 + 2 * tig;
                float* dst = (nglob < DOUT) ? g_ya : g_yb;
                int col = (nglob < DOUT) ? nglob : nglob - DOUT;
                if (r0 < NN) {
                    float2 v0 = make_float2(acc[mt][nt][0], acc[mt][nt][1]);
                    *(float2*)(dst + (size_t)r0 * DOUT + col) = v0;
                }
                if (r0 + 8 < NN) {
                    float2 v1 = make_float2(acc[mt][nt][2], acc[mt][nt][3]);
                    *(float2*)(dst + (size_t)(r0 + 8) * DOUT + col) = v1;
                }
            }
        }
    }
}

// ---------------------------------------------------------------------------
// Aggregation: one warp per node, edges unrolled x4 (independent accumulators).
// ---------------------------------------------------------------------------
template<int DO, int DST, int RELU>
__global__ void agg_kernel(float* __restrict__ out_ext, int boff) {
    int gt = blockIdx.x * blockDim.x + threadIdx.x;
    int node = gt >> 5;
    int lane = gt & 31;
    if (node >= NN) return;
    float* out = (DST == 0) ? out_ext : (DST == 1) ? g_h0 : g_h1;
    const float* bias = g_bsum + boff;

    int start = g_rowptr[node];
    int deg   = g_cnt[node];
    float inv = g_inv[node];

    if (DO == 128) {
        float4 a0 = make_float4(0.f, 0.f, 0.f, 0.f), a1 = a0, a2 = a0, a3 = a0;
        int i = 0;
        for (; i + 3 < deg; i += 4) {
            int s0 = g_csrc[start + i],     s1 = g_csrc[start + i + 1];
            int s2 = g_csrc[start + i + 2], s3 = g_csrc[start + i + 3];
            float4 v0 = *(const float4*)(g_ya + (size_t)s0 * 128 + lane * 4);
            float4 v1 = *(const float4*)(g_ya + (size_t)s1 * 128 + lane * 4);
            float4 v2 = *(const float4*)(g_ya + (size_t)s2 * 128 + lane * 4);
            float4 v3 = *(const float4*)(g_ya + (size_t)s3 * 128 + lane * 4);
            a0.x += v0.x; a0.y += v0.y; a0.z += v0.z; a0.w += v0.w;
            a1.x += v1.x; a1.y += v1.y; a1.z += v1.z; a1.w += v1.w;
            a2.x += v2.x; a2.y += v2.y; a2.z += v2.z; a2.w += v2.w;
            a3.x += v3.x; a3.y += v3.y; a3.z += v3.z; a3.w += v3.w;
        }
        for (; i < deg; ++i) {
            int s0 = g_csrc[start + i];
            float4 v0 = *(const float4*)(g_ya + (size_t)s0 * 128 + lane * 4);
            a0.x += v0.x; a0.y += v0.y; a0.z += v0.z; a0.w += v0.w;
        }
        a0.x += a1.x + a2.x + a3.x; a0.y += a1.y + a2.y + a3.y;
        a0.z += a1.z + a2.z + a3.z; a0.w += a1.w + a2.w + a3.w;
        float4 yb = *(const float4*)(g_yb + (size_t)node * 128 + lane * 4);
        float4 r;
        r.x = a0.x * inv + yb.x + bias[lane * 4 + 0];
        r.y = a0.y * inv + yb.y + bias[lane * 4 + 1];
        r.z = a0.z * inv + yb.z + bias[lane * 4 + 2];
        r.w = a0.w * inv + yb.w + bias[lane * 4 + 3];
        if (RELU) {
            r.x = fmaxf(r.x, 0.f); r.y = fmaxf(r.y, 0.f);
            r.z = fmaxf(r.z, 0.f); r.w = fmaxf(r.w, 0.f);
        }
        *(float4*)(out + (size_t)node * 128 + lane * 4) = r;
    } else {
        float2 a0 = make_float2(0.f, 0.f), a1 = a0, a2 = a0, a3 = a0;
        int i = 0;
        for (; i + 3 < deg; i += 4) {
            int s0 = g_csrc[start + i],     s1 = g_csrc[start + i + 1];
            int s2 = g_csrc[start + i + 2], s3 = g_csrc[start + i + 3];
            float2 v0 = *(const float2*)(g_ya + (size_t)s0 * 64 + lane * 2);
            float2 v1 = *(const float2*)(g_ya + (size_t)s1 * 64 + lane * 2);
            float2 v2 = *(const float2*)(g_ya + (size_t)s2 * 64 + lane * 2);
            float2 v3 = *(const float2*)(g_ya + (size_t)s3 * 64 + lane * 2);
            a0.x += v0.x; a0.y += v0.y;  a1.x += v1.x; a1.y += v1.y;
            a2.x += v2.x; a2.y += v2.y;  a3.x += v3.x; a3.y += v3.y;
        }
        for (; i < deg; ++i) {
            int s0 = g_csrc[start + i];
            float2 v0 = *(const float2*)(g_ya + (size_t)s0 * 64 + lane * 2);
            a0.x += v0.x; a0.y += v0.y;
        }
        a0.x += a1.x + a2.x + a3.x; a0.y += a1.y + a2.y + a3.y;
        float2 yb = *(const float2*)(g_yb + (size_t)node * 64 + lane * 2);
        float2 r;
        r.x = a0.x * inv + yb.x + bias[lane * 2 + 0];
        r.y = a0.y * inv + yb.y + bias[lane * 2 + 1];
        if (RELU) { r.x = fmaxf(r.x, 0.f); r.y = fmaxf(r.y, 0.f); }
        *(float2*)(out + (size_t)node * 64 + lane * 2) = r;
    }
}

// ---------------------------------------------------------------------------
extern "C" void kernel_launch(void* const* d_in, const int* in_sizes, int n_in,
                              void* d_out, int out_size) {
    const float* x  = (const float*)d_in[0];
    const void*  ei = d_in[1];
    const float* Wl0 = (const float*)d_in[4];
    const float* bl0 = (const float*)d_in[5];
    const float* Wr0 = (const float*)d_in[6];
    const float* Ws0 = (const float*)d_in[7];
    const float* bs0 = (const float*)d_in[8];
    const float* Wl1 = (const float*)d_in[9];
    const float* bl1 = (const float*)d_in[10];
    const float* Wr1 = (const float*)d_in[11];
    const float* Ws1 = (const float*)d_in[12];
    const float* bs1 = (const float*)d_in[13];
    const float* Wl2 = (const float*)d_in[14];
    const float* bl2 = (const float*)d_in[15];
    const float* Wr2 = (const float*)d_in[16];
    const float* Ws2 = (const float*)d_in[17];
    const float* bs2 = (const float*)d_in[18];
    float* out = (float*)d_out;

    const int S256 = 65536 + 2 * 256 * 256;   // 196608
    const int S128 = 65536 + 2 * 128 * 256;   // 131072
    cudaFuncSetAttribute(tc_gemm_kernel<256, 128, 0>, cudaFuncAttributeMaxDynamicSharedMemorySize, S256);
    cudaFuncSetAttribute(tc_gemm_kernel<256, 128, 1>, cudaFuncAttributeMaxDynamicSharedMemorySize, S256);
    cudaFuncSetAttribute(tc_gemm_kernel<128, 64, 2>,  cudaFuncAttributeMaxDynamicSharedMemorySize, S128);

    const int eBlocks    = (EE + 255) / 256;
    const int gemmBlocks = (NN + 127) / 128;     // 391
    const int aggBlocks  = (NN * 32) / 256;      // 6250
    const int scanBlocks = (NN + 255) / 256;     // 196

    // Order: tc_gemm L0 stays at launch #3 (0-based) for ncu
    prepb_kernel<<<322, 256>>>(Wl0, Wr0, Ws0, Wl1, Wr1, Ws1, Wl2, Wr2, Ws2,
                               bl0, bs0, bl1, bs1, bl2, bs2);               // 0
    zero_cnt_kernel<<<scanBlocks, 256>>>();                                  // 1
    detect_kernel<<<1, 32>>>((const long long*)ei);                          // 2

    tc_gemm_kernel<256, 128, 0><<<gemmBlocks, 512, S256>>>(x, 0);            // 3 (profiled)

    convert_count_kernel<<<eBlocks, 256>>>(ei);                              // 4
    scanA_kernel<<<scanBlocks, 256>>>();                                     // 5
    scanB_kernel<<<1, 256>>>(scanBlocks);                                    // 6
    scanC_kernel<<<scanBlocks, 256>>>();                                     // 7
    fill_kernel<<<eBlocks, 256>>>();                                         // 8

    agg_kernel<128, 1, 1><<<aggBlocks, 256>>>(nullptr, 0);                   // 9

    tc_gemm_kernel<256, 128, 1><<<gemmBlocks, 512, S256>>>(nullptr, 131072); // 10
    agg_kernel<128, 2, 1><<<aggBlocks, 256>>>(nullptr, DD);                  // 11

    tc_gemm_kernel<128, 64, 2><<<gemmBlocks, 512, S128>>>(nullptr, 262144);  // 12
    agg_kernel<64, 0, 0><<<aggBlocks, 256>>>(out, 2 * DD);                   // 13
}